// round 6
// baseline (speedup 1.0000x reference)
#include <cuda_runtime.h>
#include <cuda_bf16.h>
#include <cstdint>
#include <cstddef>

// ===================== problem constants =====================
#define TOKENS 4096
#define HID    1024
#define NEXP   8
#define GUP    2048
#define KTOT   8192          // NEXP*1024

// ===================== GEMM tiling =====================
#define BM     128
#define BN     128
#define BK     32
#define STAGES 4
#define THREADS 256

#define ASTRIDE 36               // floats per A smem row (conflict-free, 16B-aligned)
#define BSTRIDE 136              // floats per B smem row
#define A_STAGE (BM*ASTRIDE)     // 4608 floats
#define B_STAGE (BK*BSTRIDE)     // 4352 floats
#define STAGE_FLOATS (A_STAGE + B_STAGE)          // 8960
#define SMEM_BYTES   (STAGES*STAGE_FLOATS*4)      // 143360

// ===================== device scratch =====================
__device__ __align__(1024) float g_ACT  [(size_t)TOKENS*KTOT];  // 128 MB
__device__ __align__(1024) float g_BIAS2[(size_t)TOKENS*HID];   // 16 MB

// ===================== PTX helpers =====================
__device__ __forceinline__ uint32_t f2tf(float x) {
    uint32_t u;
    asm("cvt.rna.tf32.f32 %0, %1;" : "=r"(u) : "f"(x));
    return u;
}

__device__ __forceinline__ void mma8(float* c, const uint32_t* a, const uint32_t* b) {
    asm volatile(
        "mma.sync.aligned.m16n8k8.row.col.f32.tf32.tf32.f32 "
        "{%0,%1,%2,%3}, {%4,%5,%6,%7}, {%8,%9}, {%0,%1,%2,%3};"
        : "+f"(c[0]), "+f"(c[1]), "+f"(c[2]), "+f"(c[3])
        : "r"(a[0]), "r"(a[1]), "r"(a[2]), "r"(a[3]), "r"(b[0]), "r"(b[1]));
}

#define CP16(dst, src) \
    asm volatile("cp.async.cg.shared.global [%0], [%1], 16;" :: "r"(dst), "l"(src))
#define CP_COMMIT() asm volatile("cp.async.commit_group;" ::: "memory")
#define CP_WAIT2()  asm volatile("cp.async.wait_group %0;" :: "n"(STAGES - 2) : "memory")

// ===================== stage loader =====================
__device__ __forceinline__ void load_stage(uint32_t sbase, int stage,
                                           const float* __restrict__ Ab, int lda,
                                           const float* __restrict__ Bb, int ldb,
                                           int k0, int tid) {
    uint32_t sA = sbase + (uint32_t)(stage * STAGE_FLOATS) * 4u;
    uint32_t sB = sA + (uint32_t)A_STAGE * 4u;
    #pragma unroll
    for (int i = 0; i < 4; i++) {                 // A: 128 rows x 32 floats
        int id  = tid + i * THREADS;
        int row = id >> 3;
        int c4  = (id & 7) * 4;
        CP16(sA + (uint32_t)(row * ASTRIDE + c4) * 4u,
             Ab + (size_t)row * lda + k0 + c4);
    }
    #pragma unroll
    for (int i = 0; i < 4; i++) {                 // B: 32 rows x 128 floats
        int id  = tid + i * THREADS;
        int row = id >> 5;
        int c4  = (id & 31) * 4;
        CP16(sB + (uint32_t)(row * BSTRIDE + c4) * 4u,
             Bb + (size_t)(k0 + row) * ldb + c4);
    }
    CP_COMMIT();
}

// ===================== fused GEMM kernel =====================
// EPI=1: GEMM1 (X @ W1, K=1024) -> bias + clamp + SiLU-GLU + rw scale -> ACT
// EPI=2: GEMM2 (ACT @ W2, K=8192) -> + BIAS2 -> out
template <int EPI>
__global__ void __launch_bounds__(THREADS, 1)
gemm_kernel(const float* __restrict__ Aglob,   // X or ACT
            const float* __restrict__ Bglob,   // W1 or W2
            const float* __restrict__ b1,      // [8][2048]   (EPI=1)
            const float* __restrict__ rw,      // [4096][8]   (EPI=1)
            const float* __restrict__ bias2,   // [4096][1024](EPI=2)
            float* __restrict__ outp)          // ACT or out
{
    constexpr int KTOTAL = (EPI == 1) ? HID : KTOT;
    constexpr int KT     = KTOTAL / BK;
    constexpr int LDA    = (EPI == 1) ? HID : KTOT;

    extern __shared__ __align__(16) float sm[];
    uint32_t sbase = (uint32_t)__cvta_generic_to_shared(sm);

    const int tid  = threadIdx.x;
    const int lane = tid & 31;
    const int w    = tid >> 5;
    const int mw   = (w >> 2) * 64;     // warp M offset (0,64)
    const int nw   = (w & 3) * 32;      // warp N offset (0..96)
    const int gid  = lane >> 2;         // 0..7
    const int tig  = lane & 3;          // 0..3

    const int m0    = blockIdx.x * BM;
    const int nglob = blockIdx.y * BN;

    const float* Ab = Aglob + (size_t)m0 * LDA;
    const float* Bb;
    int ldb, e = 0, g0 = 0;
    if (EPI == 1) {
        e  = nglob >> 11;               // expert (2048 cols each)
        g0 = nglob & (GUP - 1);
        Bb  = Bglob + (size_t)e * HID * GUP + g0;
        ldb = GUP;
    } else {
        Bb  = Bglob + nglob;            // W2 flattened [8192][1024], contiguous in k
        ldb = HID;
    }

    float c[4][4][4];
    #pragma unroll
    for (int i = 0; i < 4; i++)
        #pragma unroll
        for (int j = 0; j < 4; j++)
            #pragma unroll
            for (int r = 0; r < 4; r++) c[i][j][r] = 0.0f;

    #pragma unroll
    for (int s = 0; s < STAGES - 1; s++)
        load_stage(sbase, s, Ab, LDA, Bb, ldb, s * BK, tid);

    #pragma unroll 1
    for (int kt = 0; kt < KT; kt++) {
        CP_WAIT2();
        __syncthreads();
        if (kt + STAGES - 1 < KT)
            load_stage(sbase, (kt + STAGES - 1) & (STAGES - 1), Ab, LDA, Bb, ldb,
                       (kt + STAGES - 1) * BK, tid);

        const float* As = sm + (kt & (STAGES - 1)) * STAGE_FLOATS;
        const float* Bs = As + A_STAGE;

        #pragma unroll
        for (int ks = 0; ks < 4; ks++) {
            const int kk = ks * 8;
            uint32_t a[4][4];
            #pragma unroll
            for (int mf = 0; mf < 4; mf++) {
                int r0 = mw + mf * 16 + gid;
                a[mf][0] = f2tf(As[r0 * ASTRIDE + kk + tig]);
                a[mf][1] = f2tf(As[(r0 + 8) * ASTRIDE + kk + tig]);
                a[mf][2] = f2tf(As[r0 * ASTRIDE + kk + tig + 4]);
                a[mf][3] = f2tf(As[(r0 + 8) * ASTRIDE + kk + tig + 4]);
            }
            uint32_t b[4][2];
            #pragma unroll
            for (int nf = 0; nf < 4; nf++) {
                int n = nw + nf * 8 + gid;
                b[nf][0] = f2tf(Bs[(kk + tig) * BSTRIDE + n]);
                b[nf][1] = f2tf(Bs[(kk + tig + 4) * BSTRIDE + n]);
            }
            #pragma unroll
            for (int mf = 0; mf < 4; mf++)
                #pragma unroll
                for (int nf = 0; nf < 4; nf++)
                    mma8(c[mf][nf], a[mf], b[nf]);
        }
        __syncthreads();
    }

    // ===================== epilogue =====================
    if (EPI == 1) {
        #pragma unroll
        for (int mf = 0; mf < 4; mf++) {
            #pragma unroll
            for (int h = 0; h < 2; h++) {
                int t = m0 + mw + mf * 16 + h * 8 + gid;
                float rwv = rw[t * NEXP + e];
                float* actp = outp + (size_t)t * KTOT + e * 1024;
                #pragma unroll
                for (int nf = 0; nf < 4; nf++) {
                    int gcol = g0 + nw + nf * 8 + 2 * tig;  // even = gate
                    float2 bv = *(const float2*)(b1 + e * GUP + gcol);
                    float g = c[mf][nf][h * 2 + 0] + bv.x;
                    float u = c[mf][nf][h * 2 + 1] + bv.y;
                    g = fminf(g, 7.0f);
                    u = fminf(fmaxf(u, -7.0f), 7.0f);
                    float glu = g / (1.0f + __expf(-1.702f * g));
                    actp[gcol >> 1] = (u + 1.0f) * glu * rwv;
                }
            }
        }
    } else {
        #pragma unroll
        for (int mf = 0; mf < 4; mf++) {
            #pragma unroll
            for (int h = 0; h < 2; h++) {
                int t = m0 + mw + mf * 16 + h * 8 + gid;
                const float* bp = bias2 + (size_t)t * HID + nglob;
                float* op = outp + (size_t)t * HID + nglob;
                #pragma unroll
                for (int nf = 0; nf < 4; nf++) {
                    int n = nw + nf * 8 + 2 * tig;
                    float2 bv = *(const float2*)(bp + n);
                    float2 ov;
                    ov.x = c[mf][nf][h * 2 + 0] + bv.x;
                    ov.y = c[mf][nf][h * 2 + 1] + bv.y;
                    *(float2*)(op + n) = ov;
                }
            }
        }
    }
}

// ===================== bias2 = rw @ b2 =====================
__global__ void bias2_kernel(const float* __restrict__ rw,
                             const float* __restrict__ b2,
                             float* __restrict__ bias2) {
    int h = blockIdx.x * 256 + threadIdx.x;
    int t = blockIdx.y;
    float s = 0.0f;
    #pragma unroll
    for (int e = 0; e < NEXP; e++) s += rw[t * NEXP + e] * b2[e * HID + h];
    bias2[(size_t)t * HID + h] = s;
}

// ===================== host =====================
extern "C" void kernel_launch(void* const* d_in, const int* in_sizes, int n_in,
                              void* d_out, int out_size) {
    const float* X  = (const float*)d_in[0];  // [4096][1024]
    const float* RW = (const float*)d_in[1];  // [4096][8]
    const float* W1 = (const float*)d_in[2];  // [8][1024][2048]
    const float* B1 = (const float*)d_in[3];  // [8][2048]
    const float* W2 = (const float*)d_in[4];  // [8][1024][1024]
    const float* B2 = (const float*)d_in[5];  // [8][1024]
    float* OUT = (float*)d_out;

    float *ACT, *BIAS2;
    cudaGetSymbolAddress((void**)&ACT,   g_ACT);
    cudaGetSymbolAddress((void**)&BIAS2, g_BIAS2);

    cudaFuncSetAttribute(gemm_kernel<1>, cudaFuncAttributeMaxDynamicSharedMemorySize, SMEM_BYTES);
    cudaFuncSetAttribute(gemm_kernel<2>, cudaFuncAttributeMaxDynamicSharedMemorySize, SMEM_BYTES);

    bias2_kernel<<<dim3(HID / 256, TOKENS), 256>>>(RW, B2, BIAS2);

    // GEMM1: [4096 x 16384], K=1024.  blockIdx.x = M-tile (A L2-resident rasterization)
    gemm_kernel<1><<<dim3(TOKENS / BM, (NEXP * GUP) / BN), THREADS, SMEM_BYTES>>>(
        X, W1, B1, RW, nullptr, ACT);

    // GEMM2: [4096 x 1024], K=8192
    gemm_kernel<2><<<dim3(TOKENS / BM, HID / BN), THREADS, SMEM_BYTES>>>(
        ACT, W2, nullptr, nullptr, BIAS2, OUT);
}

// round 7
// speedup vs baseline: 1.4629x; 1.4629x over previous
#include <cuda_runtime.h>
#include <cuda_bf16.h>
#include <cuda.h>
#include <cstdint>
#include <cstddef>

// ===================== problem constants =====================
#define TOKENS 4096
#define HID    1024
#define NEXP   8
#define GUP    2048
#define KTOT   8192          // NEXP*1024

// ===================== GEMM tiling =====================
#define BM     128
#define BN     256
#define BK     32
#define THREADS 256

#define A_BYTES   16384      // 128 x 32 x 4
#define B_BYTES   32768      // 32 x 256 x 4
#define STG_BYTES (A_BYTES + B_BYTES)   // 49152
#define SMEM_MBAR 0
#define SMEM_DATA 1024
#define SMEM_TOTAL (SMEM_DATA + 4*STG_BYTES)   // 197632

// ===================== device scratch =====================
__device__ __align__(1024) float g_ACT  [(size_t)TOKENS*KTOT];  // 128 MB (tf32-rounded)
__device__ __align__(1024) float g_BIAS2[(size_t)TOKENS*HID];   // 16 MB
__device__ __align__(1024) float g_XR   [(size_t)TOKENS*HID];   // 16 MB (tf32-rounded X)
__device__ __align__(1024) float g_W1R  [(size_t)NEXP*HID*GUP]; // 64 MB
__device__ __align__(1024) float g_W2R  [(size_t)KTOT*HID];     // 32 MB

// ===================== PTX helpers =====================
__device__ __forceinline__ uint32_t smem_u32(const void* p) {
    uint32_t a;
    asm("{ .reg .u64 t; cvta.to.shared.u64 t, %1; cvt.u32.u64 %0, t; }" : "=r"(a) : "l"(p));
    return a;
}
__device__ __forceinline__ float tf32_rn(float x) {
    uint32_t u;
    asm("cvt.rna.tf32.f32 %0, %1;" : "=r"(u) : "f"(x));
    return __uint_as_float(u);
}
__device__ __forceinline__ void mma8(float* c, const uint32_t* a, const uint32_t* b) {
    asm volatile(
        "mma.sync.aligned.m16n8k8.row.col.f32.tf32.tf32.f32 "
        "{%0,%1,%2,%3}, {%4,%5,%6,%7}, {%8,%9}, {%0,%1,%2,%3};"
        : "+f"(c[0]), "+f"(c[1]), "+f"(c[2]), "+f"(c[3])
        : "r"(a[0]), "r"(a[1]), "r"(a[2]), "r"(a[3]), "r"(b[0]), "r"(b[1]));
}
#define LDS32(x, addr) \
    asm volatile("ld.shared.b32 %0, [%1];" : "=r"(x) : "r"(addr))

#define MBAR_INIT(addr, cnt) \
    asm volatile("mbarrier.init.shared.b64 [%0], %1;" :: "r"((uint32_t)(addr)), "r"((uint32_t)(cnt)) : "memory")
#define MBAR_EXPECT_TX(addr, bytes) \
    asm volatile("mbarrier.arrive.expect_tx.shared.b64 _, [%0], %1;" :: "r"((uint32_t)(addr)), "r"((uint32_t)(bytes)) : "memory")

#define MBAR_WAIT(addr, parity) do {                                                    \
    uint32_t _m = (uint32_t)(addr), _p = (uint32_t)(parity), _d;                        \
    asm volatile("{\n\t.reg .pred p;\n\t"                                               \
        "mbarrier.try_wait.parity.acquire.cta.shared::cta.b64 p, [%1], %2;\n\t"         \
        "selp.b32 %0, 1, 0, p;\n\t}" : "=r"(_d) : "r"(_m), "r"(_p) : "memory");         \
    if (!_d) {                                                                          \
        asm volatile("{\n\t.reg .pred P1;\n\t"                                          \
            "WLA_%=:\n\t"                                                               \
            "mbarrier.try_wait.parity.acquire.cta.shared::cta.b64 P1, [%0], %1, 0x989680;\n\t" \
            "@P1 bra.uni WDA_%=;\n\t"                                                   \
            "bra.uni WLA_%=;\n\t"                                                       \
            "WDA_%=:\n\t}" :: "r"(_m), "r"(_p) : "memory");                             \
    }                                                                                   \
} while (0)

#define TMA2D(smem_addr, tmap, cx, cy, mbar) \
    asm volatile("cp.async.bulk.tensor.2d.shared::cta.global.tile.mbarrier::complete_tx::bytes " \
        "[%0], [%1, {%2, %3}], [%4];" \
        :: "r"((uint32_t)(smem_addr)), "l"(tmap), "r"((int32_t)(cx)), "r"((int32_t)(cy)), \
           "r"((uint32_t)(mbar)) : "memory")
#define TMA3D(smem_addr, tmap, cx, cy, cz, mbar) \
    asm volatile("cp.async.bulk.tensor.3d.shared::cta.global.tile.mbarrier::complete_tx::bytes " \
        "[%0], [%1, {%2, %3, %4}], [%5];" \
        :: "r"((uint32_t)(smem_addr)), "l"(tmap), "r"((int32_t)(cx)), "r"((int32_t)(cy)), \
           "r"((int32_t)(cz)), "r"((uint32_t)(mbar)) : "memory")

// ===================== fused GEMM kernel =====================
// EPI=1: GEMM1 (Xr @ W1r, K=1024, B 3D over experts) -> act epilogue -> ACT (rounded)
// EPI=2: GEMM2 (ACT @ W2r, K=8192, B 2D)             -> + BIAS2 -> out
template <int KT, bool B3D, int EPI>
__global__ void __launch_bounds__(THREADS, 1)
gemm_kernel(const __grid_constant__ CUtensorMap mA,
            const __grid_constant__ CUtensorMap mB,
            const float* __restrict__ b1,      // [8][2048]    (EPI=1)
            const float* __restrict__ rw,      // [4096][8]    (EPI=1)
            const float* __restrict__ bias2,   // [4096][1024] (EPI=2)
            float* __restrict__ outp)
{
    extern __shared__ __align__(1024) char smem[];
    uint32_t sb = smem_u32(smem);

    const int tid  = threadIdx.x;
    const int lane = tid & 31;
    const int w    = tid >> 5;
    const int mw   = (w >> 2) * 64;     // warp M offset (0,64)
    const int nw   = (w & 3) * 64;      // warp N offset (0,64,128,192)
    const int gid  = lane >> 2;         // 0..7
    const int tig  = lane & 3;          // 0..3

    const int m0    = blockIdx.x * BM;
    const int nglob = blockIdx.y * BN;
    int e = 0, nb;
    if (B3D) { e = nglob >> 11; nb = nglob & (GUP - 1); }
    else     { nb = nglob; }

    if (tid == 0) {
        #pragma unroll
        for (int i = 0; i < 4; i++) MBAR_INIT(sb + SMEM_MBAR + i * 8, 1);
    }
    __syncthreads();

    auto issue = [&](int s) {
        int b = s & 3, k0 = s * BK;
        uint32_t mb  = sb + SMEM_MBAR + b * 8;
        uint32_t dst = sb + SMEM_DATA + b * STG_BYTES;
        MBAR_EXPECT_TX(mb, STG_BYTES);
        TMA2D(dst, &mA, k0, m0, mb);                       // A tile [128m x 32k], SW128
        #pragma unroll
        for (int c = 0; c < 8; c++) {                      // B tile in 8 [32k x 32n] chunks
            if (B3D) TMA3D(dst + A_BYTES + c * 4096, &mB, nb + c * 32, k0, e, mb);
            else     TMA2D(dst + A_BYTES + c * 4096, &mB, nb + c * 32, k0, mb);
        }
    };

    if (tid == 0) { issue(0); issue(1); issue(2); }

    float acc[4][8][4];
    #pragma unroll
    for (int i = 0; i < 4; i++)
        #pragma unroll
        for (int j = 0; j < 8; j++)
            #pragma unroll
            for (int r = 0; r < 4; r++) acc[i][j][r] = 0.0f;

    const uint32_t aXor = (uint32_t)gid << 4;   // A swizzle xor (row&7 == gid for all frags)

    #pragma unroll 1
    for (int kt = 0; kt < KT; kt++) {
        int b = kt & 3;
        MBAR_WAIT(sb + SMEM_MBAR + b * 8, (kt >> 2) & 1);
        __syncthreads();                          // prior stage fully consumed by all threads
        if (tid == 0 && kt + 3 < KT) issue(kt + 3);

        uint32_t sA = sb + SMEM_DATA + b * STG_BYTES;
        uint32_t sB = sA + A_BYTES;

        #pragma unroll
        for (int ks = 0; ks < 4; ks++) {
            const int kk = ks * 8;
            const uint32_t kx0 = ((uint32_t)((kk + tig) * 4)) ^ aXor;
            const uint32_t kx1 = ((uint32_t)((kk + tig + 4) * 4)) ^ aXor;
            uint32_t a[4][4];
            #pragma unroll
            for (int mf = 0; mf < 4; mf++) {
                uint32_t base0 = sA + (uint32_t)((mw + mf * 16 + gid) * 128);
                uint32_t base1 = base0 + 8 * 128;
                LDS32(a[mf][0], base0 + kx0);
                LDS32(a[mf][1], base1 + kx0);
                LDS32(a[mf][2], base0 + kx1);
                LDS32(a[mf][3], base1 + kx1);
            }
            uint32_t bf[8][2];
            #pragma unroll
            for (int nf = 0; nf < 8; nf++) {
                int n  = nw + nf * 8 + gid;
                int c  = n >> 5, nn = n & 31;
                uint32_t x0 = ((uint32_t)(nn * 4)) ^ ((uint32_t)tig << 4);
                uint32_t x1 = ((uint32_t)(nn * 4)) ^ (((uint32_t)tig + 4u) << 4);
                uint32_t cb = sB + (uint32_t)(c * 4096);
                LDS32(bf[nf][0], cb + (uint32_t)((kk + tig) * 128) + x0);
                LDS32(bf[nf][1], cb + (uint32_t)((kk + tig + 4) * 128) + x1);
            }
            #pragma unroll
            for (int mf = 0; mf < 4; mf++)
                #pragma unroll
                for (int nf = 0; nf < 8; nf++)
                    mma8(acc[mf][nf], a[mf], bf[nf]);
        }
    }

    // ===================== epilogue =====================
    if (EPI == 1) {
        #pragma unroll
        for (int mf = 0; mf < 4; mf++) {
            #pragma unroll
            for (int h = 0; h < 2; h++) {
                int t = m0 + mw + mf * 16 + h * 8 + gid;
                float rwv = rw[t * NEXP + e];
                float* actp = outp + (size_t)t * KTOT + e * 1024;
                #pragma unroll
                for (int nf = 0; nf < 8; nf++) {
                    int gcol = nb + nw + nf * 8 + 2 * tig;   // even = gate, odd = up
                    float2 bv = *(const float2*)(b1 + e * GUP + gcol);
                    float g = acc[mf][nf][h * 2 + 0] + bv.x;
                    float u = acc[mf][nf][h * 2 + 1] + bv.y;
                    g = fminf(g, 7.0f);
                    u = fminf(fmaxf(u, -7.0f), 7.0f);
                    float glu = g / (1.0f + __expf(-1.702f * g));
                    actp[gcol >> 1] = tf32_rn((u + 1.0f) * glu * rwv);
                }
            }
        }
    } else {
        #pragma unroll
        for (int mf = 0; mf < 4; mf++) {
            #pragma unroll
            for (int h = 0; h < 2; h++) {
                int t = m0 + mw + mf * 16 + h * 8 + gid;
                const float* bp = bias2 + (size_t)t * HID + nglob;
                float* op = outp + (size_t)t * HID + nglob;
                #pragma unroll
                for (int nf = 0; nf < 8; nf++) {
                    int n = nw + nf * 8 + 2 * tig;
                    float2 bv = *(const float2*)(bp + n);
                    float2 ov;
                    ov.x = acc[mf][nf][h * 2 + 0] + bv.x;
                    ov.y = acc[mf][nf][h * 2 + 1] + bv.y;
                    *(float2*)(op + n) = ov;
                }
            }
        }
    }
}

// ===================== prep kernels =====================
__global__ void round_kernel(const float4* __restrict__ in, float4* __restrict__ out, int n4) {
    int i = blockIdx.x * 256 + threadIdx.x;
    if (i < n4) {
        float4 v = in[i];
        v.x = tf32_rn(v.x); v.y = tf32_rn(v.y); v.z = tf32_rn(v.z); v.w = tf32_rn(v.w);
        out[i] = v;
    }
}

__global__ void bias2_kernel(const float* __restrict__ rw,
                             const float* __restrict__ b2,
                             float* __restrict__ bias2) {
    int h = blockIdx.x * 256 + threadIdx.x;
    int t = blockIdx.y;
    float s = 0.0f;
    #pragma unroll
    for (int e = 0; e < NEXP; e++) s += rw[t * NEXP + e] * b2[e * HID + h];
    bias2[(size_t)t * HID + h] = s;
}

// ===================== host side =====================
typedef CUresult (CUDAAPI *PFN_encodeTiled)(
    CUtensorMap*, CUtensorMapDataType, cuuint32_t, void*,
    const cuuint64_t*, const cuuint64_t*, const cuuint32_t*, const cuuint32_t*,
    CUtensorMapInterleave, CUtensorMapSwizzle, CUtensorMapL2promotion, CUtensorMapFloatOOBfill);

static PFN_encodeTiled get_encode_fn() {
    void* fp = nullptr;
    cudaDriverEntryPointQueryResult qr;
#if CUDART_VERSION >= 12050
    cudaGetDriverEntryPointByVersion("cuTensorMapEncodeTiled", &fp, 12000, cudaEnableDefault, &qr);
#else
    cudaGetDriverEntryPoint("cuTensorMapEncodeTiled", &fp, cudaEnableDefault, &qr);
#endif
    return (PFN_encodeTiled)fp;
}

static CUtensorMap make_map(PFN_encodeTiled enc, void* p, int nd,
                            uint64_t d0, uint64_t d1, uint64_t d2,
                            uint32_t b0, uint32_t b1) {
    CUtensorMap m;
    cuuint64_t dims[3]    = {d0, d1, d2};
    cuuint64_t strides[2] = {d0 * 4, d0 * d1 * 4};
    cuuint32_t box[3]     = {b0, b1, 1};
    cuuint32_t es[3]      = {1, 1, 1};
    enc(&m, CU_TENSOR_MAP_DATA_TYPE_FLOAT32, nd, p, dims, strides, box, es,
        CU_TENSOR_MAP_INTERLEAVE_NONE, CU_TENSOR_MAP_SWIZZLE_128B,
        CU_TENSOR_MAP_L2_PROMOTION_L2_128B, CU_TENSOR_MAP_FLOAT_OOB_FILL_NONE);
    return m;
}

extern "C" void kernel_launch(void* const* d_in, const int* in_sizes, int n_in,
                              void* d_out, int out_size) {
    const float* X  = (const float*)d_in[0];  // [4096][1024]
    const float* RW = (const float*)d_in[1];  // [4096][8]
    const float* W1 = (const float*)d_in[2];  // [8][1024][2048]
    const float* B1 = (const float*)d_in[3];  // [8][2048]
    const float* W2 = (const float*)d_in[4];  // [8][1024][1024]
    const float* B2 = (const float*)d_in[5];  // [8][1024]
    float* OUT = (float*)d_out;

    float *ACT, *BIAS2, *XR, *W1R, *W2R;
    cudaGetSymbolAddress((void**)&ACT,   g_ACT);
    cudaGetSymbolAddress((void**)&BIAS2, g_BIAS2);
    cudaGetSymbolAddress((void**)&XR,    g_XR);
    cudaGetSymbolAddress((void**)&W1R,   g_W1R);
    cudaGetSymbolAddress((void**)&W2R,   g_W2R);

    PFN_encodeTiled enc = get_encode_fn();
    // A1: Xr [4096][1024], box {32k, 128m}
    CUtensorMap mA1 = make_map(enc, XR,  2, HID,  TOKENS, 1,    BK, BM);
    // B1: W1r [8][1024][2048], box {32n, 32k}
    CUtensorMap mB1 = make_map(enc, W1R, 3, GUP,  HID,    NEXP, 32, BK);
    // A2: ACT [4096][8192], box {32k, 128m}
    CUtensorMap mA2 = make_map(enc, ACT, 2, KTOT, TOKENS, 1,    BK, BM);
    // B2: W2r as [8192][1024], box {32n, 32k}
    CUtensorMap mB2 = make_map(enc, W2R, 2, HID,  KTOT,   1,    32, BK);

    cudaFuncSetAttribute((const void*)gemm_kernel<HID/BK,  true,  1>,
                         cudaFuncAttributeMaxDynamicSharedMemorySize, SMEM_TOTAL);
    cudaFuncSetAttribute((const void*)gemm_kernel<KTOT/BK, false, 2>,
                         cudaFuncAttributeMaxDynamicSharedMemorySize, SMEM_TOTAL);

    // prep: tf32 rounding + fused bias
    round_kernel<<<TOKENS * HID / 4 / 256, 256>>>((const float4*)X,  (float4*)XR,  TOKENS * HID / 4);
    round_kernel<<<NEXP * HID * GUP / 4 / 256, 256>>>((const float4*)W1, (float4*)W1R, NEXP * HID * GUP / 4);
    round_kernel<<<KTOT * HID / 4 / 256, 256>>>((const float4*)W2, (float4*)W2R, KTOT * HID / 4);
    bias2_kernel<<<dim3(HID / 256, TOKENS), 256>>>(RW, B2, BIAS2);

    // GEMM1: [4096 x 16384], K=1024
    gemm_kernel<HID/BK, true, 1><<<dim3(TOKENS / BM, (NEXP * GUP) / BN), THREADS, SMEM_TOTAL>>>(
        mA1, mB1, B1, RW, nullptr, ACT);

    // GEMM2: [4096 x 1024], K=8192 (single wave: 128 CTAs)
    gemm_kernel<KTOT/BK, false, 2><<<dim3(TOKENS / BM, HID / BN), THREADS, SMEM_TOTAL>>>(
        mA2, mB2, nullptr, nullptr, BIAS2, OUT);
}